// round 8
// baseline (speedup 1.0000x reference)
#include <cuda_runtime.h>
#include <math.h>

// LIF scan: B=8, T=64, C=64, H=32, W=32.
// Best-measured structure (R4): float2/thread, 1024 blocks x 256, CHUNK=4.
// Added: chunk-level double buffering -- next chunk's 4 loads are issued
// BEFORE current chunk's compute+stores, so loads stay in flight during the
// store burst (raises DRAM duty cycle). Outer loop fully unrolled so the
// ping-pong is register renaming only.

#define B_ 8
#define T_ 64
#define CHW_ 65536              // 64*32*32
#define CHW2_ (CHW_ / 2)        // 32768 float2 per (b,t) slab
#define N2_ (B_ * CHW2_)        // 262144 threads
#define CHUNK_ 4

__global__ __launch_bounds__(256) void lif_scan_kernel(
    const float2* __restrict__ x,        // [B*T*CHW2] float2
    const float2* __restrict__ vth_raw,  // [CHW2]
    const float2* __restrict__ decay_raw,// [CHW2]
    const float* __restrict__ hp_v_m,
    const float* __restrict__ hp_v_s,
    const float* __restrict__ hp_d_m,
    const float* __restrict__ hp_d_s,
    float2* __restrict__ out)            // [B*T*CHW2] float2
{
    int tid = blockIdx.x * blockDim.x + threadIdx.x;
    if (tid >= N2_) return;

    int b = tid >> 15;          // tid / CHW2_
    int j = tid & (CHW2_ - 1);  // tid % CHW2_

    float vm = *hp_v_m, vs = *hp_v_s;
    float dm = *hp_d_m, ds = *hp_d_s;

    float2 vr = vth_raw[j];
    float2 dr = decay_raw[j];

    float vth0, vth1, dec0, dec1;
    {
        float z0 = vr.x * vs + vm, z1 = vr.y * vs + vm;
        float d0 = dr.x * ds + dm, d1 = dr.y * ds + dm;
        vth0 = ((z0 > 20.0f) ? z0 : log1pf(__expf(z0))) + 0.5f;
        vth1 = ((z1 > 20.0f) ? z1 : log1pf(__expf(z1))) + 0.5f;
        dec0 = fminf(fmaxf(1.0f / (1.0f + __expf(-d0)), 0.0f), 0.99f);
        dec1 = fminf(fmaxf(1.0f / (1.0f + __expf(-d1)), 0.0f), 0.99f);
    }

    const float2* xp = x + (size_t)b * T_ * CHW2_ + j;
    float2* op = out + (size_t)b * T_ * CHW2_ + j;

    float v0 = 0.f, v1 = 0.f;

    // Prologue: load chunk 0.
    float2 cur[CHUNK_], nxt[CHUNK_];
    #pragma unroll
    for (int i = 0; i < CHUNK_; i++)
        cur[i] = xp[(size_t)i * CHW2_];

    #pragma unroll
    for (int t0 = 0; t0 < T_; t0 += CHUNK_) {
        // Prefetch next chunk FIRST (guard is static after full unroll).
        if (t0 + CHUNK_ < T_) {
            #pragma unroll
            for (int i = 0; i < CHUNK_; i++)
                nxt[i] = xp[(size_t)(t0 + CHUNK_ + i) * CHW2_];
        }

        // Compute current chunk.
        float2 ss[CHUNK_];
        #pragma unroll
        for (int i = 0; i < CHUNK_; i++) {
            float vv0 = fmaf(v0, dec0, cur[i].x);
            float vv1 = fmaf(v1, dec1, cur[i].y);
            float s0 = (vv0 - vth0 > 0.0f) ? 1.0f : 0.0f;
            float s1 = (vv1 - vth1 > 0.0f) ? 1.0f : 0.0f;
            v0 = vv0 - s0 * vth0;
            v1 = vv1 - s1 * vth1;
            ss[i] = make_float2(s0, s1);
        }

        // Store current chunk (next chunk's loads still in flight).
        #pragma unroll
        for (int i = 0; i < CHUNK_; i++)
            op[(size_t)(t0 + i) * CHW2_] = ss[i];

        // Swap (pure register renaming after full unroll).
        #pragma unroll
        for (int i = 0; i < CHUNK_; i++)
            cur[i] = nxt[i];
    }
}

extern "C" void kernel_launch(void* const* d_in, const int* in_sizes, int n_in,
                              void* d_out, int out_size)
{
    const float2* x         = (const float2*)d_in[0];
    const float2* vth_raw   = (const float2*)d_in[1];
    const float2* decay_raw = (const float2*)d_in[2];
    const float*  hp_v_m    = (const float*)d_in[3];
    const float*  hp_v_s    = (const float*)d_in[4];
    const float*  hp_d_m    = (const float*)d_in[5];
    const float*  hp_d_s    = (const float*)d_in[6];
    // d_in[7] = hp_alpha, unused in forward
    float2* out = (float2*)d_out;

    int threads = 256;
    int blocks = N2_ / threads;  // 1024
    lif_scan_kernel<<<blocks, threads>>>(x, vth_raw, decay_raw,
                                         hp_v_m, hp_v_s, hp_d_m, hp_d_s, out);
}

// round 9
// speedup vs baseline: 1.0112x; 1.0112x over previous
#include <cuda_runtime.h>
#include <math.h>

// LIF scan: B=8, T=64, C=64, H=32, W=32. HBM-floor kernel (~6.7 TB/s).
// Merged best-of-measured: float4/thread (R1: fewest insts, best bench) x
// 1024 blocks of 128 (R4: best wave packing). Plain cached loads/stores
// (streaming hints measured -3% DRAM). CHUNK=4 batched bursts.

#define B_ 8
#define T_ 64
#define CHW_ 65536              // 64*32*32
#define CHW4_ (CHW_ / 4)        // 16384 float4 per (b,t) slab
#define N4_ (B_ * CHW4_)        // 131072 threads
#define CHUNK_ 4

__global__ __launch_bounds__(128) void lif_scan_kernel(
    const float4* __restrict__ x,        // [B*T*CHW4] float4
    const float4* __restrict__ vth_raw,  // [CHW4]
    const float4* __restrict__ decay_raw,// [CHW4]
    const float* __restrict__ hp_v_m,
    const float* __restrict__ hp_v_s,
    const float* __restrict__ hp_d_m,
    const float* __restrict__ hp_d_s,
    float4* __restrict__ out)            // [B*T*CHW4] float4
{
    int tid = blockIdx.x * blockDim.x + threadIdx.x;
    if (tid >= N4_) return;

    int b = tid >> 14;          // tid / CHW4_
    int j = tid & (CHW4_ - 1);  // tid % CHW4_

    float vm = *hp_v_m, vs = *hp_v_s;
    float dm = *hp_d_m, ds = *hp_d_s;

    float4 vr = vth_raw[j];
    float4 dr = decay_raw[j];

    float vth[4], dec[4];
    {
        float z[4] = {vr.x * vs + vm, vr.y * vs + vm, vr.z * vs + vm, vr.w * vs + vm};
        float d[4] = {dr.x * ds + dm, dr.y * ds + dm, dr.z * ds + dm, dr.w * ds + dm};
        #pragma unroll
        for (int k = 0; k < 4; k++) {
            float zz = z[k];
            float sp = (zz > 20.0f) ? zz : log1pf(__expf(zz));
            vth[k] = sp + 0.5f;
            float sg = 1.0f / (1.0f + __expf(-d[k]));
            dec[k] = fminf(fmaxf(sg, 0.0f), 0.99f);
        }
    }

    // 32-bit offsets: max = B*T*CHW4 = 2^23 float4.
    unsigned base = (unsigned)b * (T_ * CHW4_) + (unsigned)j;
    const float4* xp = x + base;
    float4* op = out + base;

    float v[4] = {0.f, 0.f, 0.f, 0.f};

    #pragma unroll
    for (int t0 = 0; t0 < T_; t0 += CHUNK_) {
        // 4 independent LDG.128 front-issued back-to-back.
        float4 xs[CHUNK_];
        #pragma unroll
        for (int i = 0; i < CHUNK_; i++)
            xs[i] = xp[(unsigned)(t0 + i) * CHW4_];

        float4 ss[CHUNK_];
        #pragma unroll
        for (int i = 0; i < CHUNK_; i++) {
            float xv[4] = {xs[i].x, xs[i].y, xs[i].z, xs[i].w};
            float s[4];
            #pragma unroll
            for (int k = 0; k < 4; k++) {
                float vv = fmaf(v[k], dec[k], xv[k]);
                float sk = (vv - vth[k] > 0.0f) ? 1.0f : 0.0f;
                v[k] = vv - sk * vth[k];
                s[k] = sk;
            }
            ss[i] = make_float4(s[0], s[1], s[2], s[3]);
        }

        // 4 STG.128 back-to-back.
        #pragma unroll
        for (int i = 0; i < CHUNK_; i++)
            op[(unsigned)(t0 + i) * CHW4_] = ss[i];
    }
}

extern "C" void kernel_launch(void* const* d_in, const int* in_sizes, int n_in,
                              void* d_out, int out_size)
{
    const float4* x         = (const float4*)d_in[0];
    const float4* vth_raw   = (const float4*)d_in[1];
    const float4* decay_raw = (const float4*)d_in[2];
    const float*  hp_v_m    = (const float*)d_in[3];
    const float*  hp_v_s    = (const float*)d_in[4];
    const float*  hp_d_m    = (const float*)d_in[5];
    const float*  hp_d_s    = (const float*)d_in[6];
    // d_in[7] = hp_alpha, unused in forward
    float4* out = (float4*)d_out;

    int threads = 128;
    int blocks = N4_ / threads;  // 1024
    lif_scan_kernel<<<blocks, threads>>>(x, vth_raw, decay_raw,
                                         hp_v_m, hp_v_s, hp_d_m, hp_d_s, out);
}

// round 10
// speedup vs baseline: 1.0169x; 1.0056x over previous
#include <cuda_runtime.h>
#include <math.h>

// LIF scan: B=8, T=64, C=64, H=32, W=32. LTS-floor kernel (~6.7 TB/s).
// Final form from 7 measured configs: float4/thread, 1024 blocks x 128
// (best ncu: 40.48us), R1's lean rolling loop (fewest insts, 34 regs).
// Plain cached loads/stores (streaming hints measured -3% DRAM).

#define B_ 8
#define T_ 64
#define CHW_ 65536              // 64*32*32
#define CHW4_ (CHW_ / 4)        // 16384 float4 per (b,t) slab
#define N4_ (B_ * CHW4_)        // 131072 threads

__global__ __launch_bounds__(128) void lif_scan_kernel(
    const float4* __restrict__ x,        // [B*T*CHW4] float4
    const float4* __restrict__ vth_raw,  // [CHW4]
    const float4* __restrict__ decay_raw,// [CHW4]
    const float* __restrict__ hp_v_m,
    const float* __restrict__ hp_v_s,
    const float* __restrict__ hp_d_m,
    const float* __restrict__ hp_d_s,
    float4* __restrict__ out)            // [B*T*CHW4] float4
{
    int tid = blockIdx.x * blockDim.x + threadIdx.x;
    if (tid >= N4_) return;

    int b = tid >> 14;          // tid / CHW4_
    int j = tid & (CHW4_ - 1);  // tid % CHW4_

    float vm = *hp_v_m, vs = *hp_v_s;
    float dm = *hp_d_m, ds = *hp_d_s;

    float4 vr = vth_raw[j];
    float4 dr = decay_raw[j];

    float vth[4], dec[4];
    {
        float z[4] = {vr.x * vs + vm, vr.y * vs + vm, vr.z * vs + vm, vr.w * vs + vm};
        float d[4] = {dr.x * ds + dm, dr.y * ds + dm, dr.z * ds + dm, dr.w * ds + dm};
        #pragma unroll
        for (int k = 0; k < 4; k++) {
            float zz = z[k];
            float sp = (zz > 20.0f) ? zz : log1pf(__expf(zz));
            vth[k] = sp + 0.5f;
            float sg = 1.0f / (1.0f + __expf(-d[k]));
            dec[k] = fminf(fmaxf(sg, 0.0f), 0.99f);
        }
    }

    // 32-bit offsets: max = B*T*CHW4 = 2^23 float4.
    unsigned base = (unsigned)b * (T_ * CHW4_) + (unsigned)j;
    const float4* xp = x + base;
    float4* op = out + base;

    float v[4] = {0.f, 0.f, 0.f, 0.f};

    #pragma unroll 8
    for (int t = 0; t < T_; t++) {
        float4 xt = xp[(unsigned)t * CHW4_];
        float xv[4] = {xt.x, xt.y, xt.z, xt.w};
        float s[4];
        #pragma unroll
        for (int k = 0; k < 4; k++) {
            float vv = fmaf(v[k], dec[k], xv[k]);
            float sk = (vv - vth[k] > 0.0f) ? 1.0f : 0.0f;
            v[k] = vv - sk * vth[k];
            s[k] = sk;
        }
        op[(unsigned)t * CHW4_] = make_float4(s[0], s[1], s[2], s[3]);
    }
}

extern "C" void kernel_launch(void* const* d_in, const int* in_sizes, int n_in,
                              void* d_out, int out_size)
{
    const float4* x         = (const float4*)d_in[0];
    const float4* vth_raw   = (const float4*)d_in[1];
    const float4* decay_raw = (const float4*)d_in[2];
    const float*  hp_v_m    = (const float*)d_in[3];
    const float*  hp_v_s    = (const float*)d_in[4];
    const float*  hp_d_m    = (const float*)d_in[5];
    const float*  hp_d_s    = (const float*)d_in[6];
    // d_in[7] = hp_alpha, unused in forward
    float4* out = (float4*)d_out;

    int threads = 128;
    int blocks = N4_ / threads;  // 1024
    lif_scan_kernel<<<blocks, threads>>>(x, vth_raw, decay_raw,
                                         hp_v_m, hp_v_s, hp_d_m, hp_d_s, out);
}